// round 13
// baseline (speedup 1.0000x reference)
#include <cuda_runtime.h>

// Fan-beam CT forward projector — two-phase, QUAD grouping:
//  (1) setup kernel precomputes per-(view,quad) wedge coefficients + window
//  (2) main kernel: warp per 4 bins, single wedge walk, t = Q/B once per
//      pixel feeds all 4 tent weights.
constexpr int   R_      = 384;
constexpr int   C_      = 384;
constexpr int   NCOLS_  = 768;
constexpr int   V_      = 256;
constexpr float DR_     = 1.0f;
constexpr float DC_     = 1.0f;
constexpr float DSPACE_ = 1.5f;

constexpr int WARPS_PER_BLOCK = 4;
constexpr int NQUADS = NCOLS_ / 4;     // 192
constexpr int NWORK  = V_ * NQUADS;    // 49152

// per-(view,quad): [0]=(q0,qs,qp,b0) [1]=(bs,bp,alo,blo) [2]=(ahi,bhi,w0i,w1i) [3]=(drive_c,-,-,-)
__device__ float4 g_pre[NWORK * 4];

__device__ __forceinline__ void drive_window(float ahi, float bhi,
                                             float alo, float blo,
                                             int& w0, int& w1)
{
    float f0 = 0.0f, f1 = 383.0f;
    const float eps = 1e-12f;
    if (bhi > eps)        f0 = fmaxf(f0, __fdividef(-0.01f - ahi, bhi) - 1.0f);
    else if (bhi < -eps)  f1 = fminf(f1, __fdividef(-0.01f - ahi, bhi) + 1.0f);
    else if (ahi < -0.01f) { w0 = 1; w1 = 0; return; }
    const float L = 383.01f;
    if (blo > eps)        f1 = fminf(f1, __fdividef(L - alo, blo) + 1.0f);
    else if (blo < -eps)  f0 = fmaxf(f0, __fdividef(L - alo, blo) - 1.0f);
    else if (alo > L)     { w0 = 1; w1 = 0; return; }
    w0 = max(0, __float2int_ru(f0));
    w1 = min(383, __float2int_rd(f1));
}

__global__ void setup_kernel(const float* __restrict__ src_g,
                             const float* __restrict__ detc_g,
                             const float* __restrict__ u_g,
                             const float* __restrict__ center_g,
                             const float* __restrict__ cdir_g)
{
    const int idx = blockIdx.x * blockDim.x + threadIdx.x;
    if (idx >= NWORK) return;
    const int v    = idx / NQUADS;
    const int quad = idx - v * NQUADS;
    const int ib   = quad * 4;

    const float sx  = src_g [2*v+0], sy  = src_g [2*v+1];
    const float dcx = detc_g[2*v+0], dcy = detc_g[2*v+1];
    const float ux  = u_g  [2*v+0], uy  = u_g  [2*v+1];
    const float nx  = -uy,          ny  = ux;
    const float cx  = center_g[0],  cy  = center_g[1];
    const float colx = cdir_g[0],   coly = cdir_g[1];
    const float rowx = -coly,       rowy = colx;

    const float vzx = cx - 0.5f*(R_-1)*DR_*rowx - 0.5f*(C_-1)*DC_*colx;
    const float vzy = cy - 0.5f*(R_-1)*DR_*rowy - 0.5f*(C_-1)*DC_*coly;

    const float src_d = sx*nx + sy*ny;
    const float su    = sx*ux + sy*uy;
    const float K     = (dcx*nx + dcy*ny) - src_d;
    const float h     = 0.5f*(NCOLS_-1)*DSPACE_;
    const float dzx   = dcx - h*ux, dzy = dcy - h*uy;
    const float A     = su - (dzx*ux + dzy*uy);

    const float bn0 = vzx*nx + vzy*ny - src_d;
    const float dnr = DR_*(rowx*nx + rowy*ny);
    const float dnc = DC_*(colx*nx + coly*ny);
    const float bu0 = vzx*ux + vzy*uy - su;
    const float dur = DR_*(rowx*ux + rowy*uy);
    const float duc = DC_*(colx*ux + coly*uy);

    const float den_c = bn0 + 0.5f*(R_-1)*dnr + 0.5f*(C_-1)*dnc;
    const float sig   = (den_c > 0.0f) ? 1.0f : -1.0f;
    const bool  tok   = (sig * K) > 0.0f;

    // Q for bin ib; B = sig*DS*den.  Q/B = col - ib.
    const float E  = A - (float)ib * DSPACE_;
    const float q0 = sig * (E*bn0 + K*bu0);
    const float qr = sig * (E*dnr + K*dur);
    const float qc = sig * (E*dnc + K*duc);
    const float b0 = sig * DSPACE_ * bn0;
    const float br = sig * DSPACE_ * dnr;
    const float bc = sig * DSPACE_ * dnc;

    // axis from quad-central ray (bin ib+1.5)
    const float ic_f = (float)ib + 1.5f;
    const float bxp = dzx + ic_f*DSPACE_*ux - sx;
    const float byp = dzy + ic_f*DSPACE_*uy - sy;
    const float dc_comp = bxp*colx + byp*coly;
    const float dr_comp = bxp*rowx + byp*rowy;
    const bool  drive_c = fabsf(dc_comp) >= fabsf(dr_comp);

    const float qs = drive_c ? qc : qr;
    const float qp = drive_c ? qr : qc;
    const float bs = drive_c ? bc : br;
    const float bp = drive_c ? br : bc;

    // quad wedge lines: Q + B = 0 (col = ib-1), Q - 5B = 0 (col = ib+4)
    const float gm  = qp + bp;
    const float gp5 = qp - 5.0f*bp;
    const float am  = __fdividef(-(q0 + b0),      gm);
    const float bm  = __fdividef(-(qs + bs),      gm);
    const float ap  = __fdividef(-(q0 - 5.0f*b0), gp5);
    const float bp5 = __fdividef(-(qs - 5.0f*bs), gp5);
    float alo, blo, ahi, bhi;
    if (fmaf(191.5f, bm, am) <= fmaf(191.5f, bp5, ap)) {
        alo = am; blo = bm; ahi = ap; bhi = bp5;
    } else {
        alo = ap; blo = bp5; ahi = am; bhi = bm;
    }

    int w0i, w1i;
    if (tok) drive_window(ahi, bhi, alo, blo, w0i, w1i);
    else     { w0i = 1; w1i = 0; }

    float4* o = g_pre + idx * 4;
    o[0] = make_float4(q0, qs, qp, b0);
    o[1] = make_float4(bs, bp, alo, blo);
    o[2] = make_float4(ahi, bhi, __int_as_float(w0i), __int_as_float(w1i));
    o[3] = make_float4(drive_c ? 1.0f : 0.0f, 0.0f, 0.0f, 0.0f);
}

// Walk driving coordinate s (lanes strided by 32), perp coord p with
// compile-time stride PSTR; SROW is the complementary stride.
template<int PSTR, int SROW>
__device__ __forceinline__ void walk(const float* __restrict__ img,
                                     int lane, int w0i, int w1i,
                                     float q0, float qs, float qp,
                                     float b0, float bs, float bp,
                                     float alo, float blo, float ahi, float bhi,
                                     float& a0, float& a1, float& a2, float& a3)
{
    for (int s = w0i + lane; s <= w1i; s += 32) {
        const float sf  = (float)s;
        const float plo = fmaxf(fmaf(sf, blo, alo) - 0.01f, 0.0f);
        const float phi = fminf(fmaf(sf, bhi, ahi) + 0.01f, 383.0f);
        const int p0 = __float2int_ru(plo);
        const int n  = __float2int_rd(phi) - p0;
        if (n >= 0) {
            const float pf0 = (float)p0;
            const float Qb  = fmaf(pf0, qp, fmaf(sf, qs, q0));
            const float Bb  = fmaf(pf0, bp, fmaf(sf, bs, b0));
            const float* p  = img + p0*PSTR + s*SROW;
            #pragma unroll 2
            for (int k = 0; k <= n; ++k) {
                const float Qp = fmaf((float)k, qp, Qb);
                const float Bp = fmaf((float)k, bp, Bb);
                const float t  = Qp * __fdividef(1.0f, Bp);   // col - ib
                const float val = __ldg(p + k*PSTR);
                const float w0 = 1.0f - fabsf(t);
                const float w1 = 1.0f - fabsf(t - 1.0f);
                const float w2 = 1.0f - fabsf(t - 2.0f);
                const float w3 = 1.0f - fabsf(t - 3.0f);
                a0 = fmaf(fmaxf(w0, 0.0f), val, a0);
                a1 = fmaf(fmaxf(w1, 0.0f), val, a1);
                a2 = fmaf(fmaxf(w2, 0.0f), val, a2);
                a3 = fmaf(fmaxf(w3, 0.0f), val, a3);
            }
        }
    }
}

__global__ __launch_bounds__(32 * WARPS_PER_BLOCK, 10)
void fanbeam_fp_kernel(const float* __restrict__ img,
                       float* __restrict__ sino)
{
    const int v    = blockIdx.y;
    const int warp = threadIdx.x >> 5;
    const int lane = threadIdx.x & 31;
    const int quad = blockIdx.x * WARPS_PER_BLOCK + warp;   // adjacent quads
    const int ib   = quad * 4;

    const float4* pp = g_pre + (v * NQUADS + quad) * 4;
    const float4 A0 = __ldg(pp + 0);
    const float4 A1 = __ldg(pp + 1);
    const float4 A2 = __ldg(pp + 2);
    const float4 A3 = __ldg(pp + 3);

    const float q0 = A0.x, qs = A0.y, qp = A0.z, b0 = A0.w;
    const float bs = A1.x, bp = A1.y, alo = A1.z, blo = A1.w;
    const float ahi = A2.x, bhi = A2.y;
    const int   w0i = __float_as_int(A2.z);
    const int   w1i = __float_as_int(A2.w);
    const bool  drive_c = (A3.x != 0.0f);

    float a0 = 0.0f, a1 = 0.0f, a2 = 0.0f, a3 = 0.0f;

    if (w0i <= w1i) {
        if (drive_c)
            walk<C_, 1>(img, lane, w0i, w1i, q0, qs, qp, b0, bs, bp,
                        alo, blo, ahi, bhi, a0, a1, a2, a3);
        else
            walk<1, C_>(img, lane, w0i, w1i, q0, qs, qp, b0, bs, bp,
                        alo, blo, ahi, bhi, a0, a1, a2, a3);
    }

    #pragma unroll
    for (int off = 16; off > 0; off >>= 1) {
        a0 += __shfl_xor_sync(0xffffffffu, a0, off);
        a1 += __shfl_xor_sync(0xffffffffu, a1, off);
        a2 += __shfl_xor_sync(0xffffffffu, a2, off);
        a3 += __shfl_xor_sync(0xffffffffu, a3, off);
    }

    if (lane == 0) {
        float* o = sino + v*NCOLS_ + ib;
        o[0] = a0; o[1] = a1; o[2] = a2; o[3] = a3;
    }
}

extern "C" void kernel_launch(void* const* d_in, const int* in_sizes, int n_in,
                              void* d_out, int out_size)
{
    const float* img    = (const float*)d_in[0];
    const float* src    = (const float*)d_in[1];
    const float* detc   = (const float*)d_in[2];
    const float* u      = (const float*)d_in[3];
    const float* center = (const float*)d_in[4];
    const float* cdir   = (const float*)d_in[5];
    float* sino = (float*)d_out;

    setup_kernel<<<(NWORK + 255) / 256, 256>>>(src, detc, u, center, cdir);

    dim3 grid(NQUADS / WARPS_PER_BLOCK, V_);
    dim3 block(32 * WARPS_PER_BLOCK);
    fanbeam_fp_kernel<<<grid, block>>>(img, sino);
}